// round 3
// baseline (speedup 1.0000x reference)
#include <cuda_runtime.h>
#include <math.h>

#define BH    8
#define DK    64
#define DVV   64
#define NSEQ  2048
#define MF    128
#define CHUNK 128
#define NC    16

#define PHI_SCALE 0.08838834764831845f   // 1/sqrt(128)

// Scratch: per-(head,chunk) state S (M x DV) and z (M), converted in-place to
// exclusive prefix sums by kernel B.
__device__ float g_S[BH * NC * MF * DVV];   // 4 MB
__device__ float g_z[BH * NC * MF];         // 64 KB

// ---------------------------------------------------------------------------
// Kernel A: per (head, chunk): phi_k = relu(K^T F^T)*s ; S = phi_k^T V ; z = sum
// ---------------------------------------------------------------------------
// smem float offsets
#define A_OFF_K    0                     // sK  [d][i]   64x128
#define A_OFF_F    8192                  // sF  [d][m]   64x132 (padded)
#define A_OFF_PHI  16640                 // sPhi[i][m]  128x132 (padded)
#define A_OFF_VT   33536                 // sVt [i][vd] 128x68  (padded)
#define A_SMEM_FLOATS 42240
#define A_SMEM_BYTES  (A_SMEM_FLOATS * 4)

__global__ void __launch_bounds__(256, 1)
kA(const float* __restrict__ keys, const float* __restrict__ values,
   const float* __restrict__ feat)
{
    const int c = blockIdx.x, h = blockIdx.y, t = threadIdx.x;
    extern __shared__ float sm[];
    float* sK   = sm + A_OFF_K;
    float* sF   = sm + A_OFF_F;
    float* sPhi = sm + A_OFF_PHI;
    float* sVt  = sm + A_OFF_VT;
    const int nbase = c * CHUNK;

    // Stage K chunk [d][i] (coalesced), V chunk transposed [i][vd], F transposed [d][m]
    for (int idx = t; idx < DK * CHUNK; idx += 256) {
        int d = idx >> 7, i = idx & 127;
        sK[idx]         = keys  [(h * DK  + d) * NSEQ + nbase + i];
        sVt[i * 68 + d] = values[(h * DVV + d) * NSEQ + nbase + i];
    }
    for (int idx = t; idx < MF * DK; idx += 256) {
        int m = idx >> 6, d = idx & 63;
        sF[d * 132 + m] = feat[idx];
    }
    __syncthreads();

    const int tx = t & 15, ty = t >> 4;

    // GEMM1: phi[i][m] = relu(sum_d K[d][i] * F[m][d]) * s   (8x8 register tile)
    {
        float acc[8][8];
        #pragma unroll
        for (int r = 0; r < 8; r++)
            #pragma unroll
            for (int cc = 0; cc < 8; cc++) acc[r][cc] = 0.f;

        const int i0 = ty * 8, m0 = tx * 8;
        for (int d = 0; d < DK; d++) {
            float a[8], b[8];
            #pragma unroll
            for (int r = 0; r < 8; r++)  a[r]  = sK[d * 128 + i0 + r];
            #pragma unroll
            for (int cc = 0; cc < 8; cc++) b[cc] = sF[d * 132 + m0 + cc];
            #pragma unroll
            for (int r = 0; r < 8; r++)
                #pragma unroll
                for (int cc = 0; cc < 8; cc++)
                    acc[r][cc] = fmaf(a[r], b[cc], acc[r][cc]);
        }
        #pragma unroll
        for (int r = 0; r < 8; r++)
            #pragma unroll
            for (int cc = 0; cc < 8; cc++)
                sPhi[(i0 + r) * 132 + m0 + cc] = fmaxf(acc[r][cc], 0.f) * PHI_SCALE;
    }
    __syncthreads();

    // GEMM2: S[m][vd] = sum_i phi[i][m] * V[i][vd]; z[m] = sum_i phi[i][m]
    {
        float acc[8][4], zacc[8];
        #pragma unroll
        for (int r = 0; r < 8; r++) {
            zacc[r] = 0.f;
            #pragma unroll
            for (int cc = 0; cc < 4; cc++) acc[r][cc] = 0.f;
        }
        const int m0 = ty * 8, v0 = tx * 4;
        for (int i = 0; i < CHUNK; i++) {
            float a[8], b[4];
            #pragma unroll
            for (int r = 0; r < 8; r++)  a[r]  = sPhi[i * 132 + m0 + r];
            #pragma unroll
            for (int cc = 0; cc < 4; cc++) b[cc] = sVt[i * 68 + v0 + cc];
            #pragma unroll
            for (int r = 0; r < 8; r++) {
                zacc[r] += a[r];
                #pragma unroll
                for (int cc = 0; cc < 4; cc++)
                    acc[r][cc] = fmaf(a[r], b[cc], acc[r][cc]);
            }
        }
        float* Sg = g_S + (size_t)((h * NC + c) * MF) * DVV;
        #pragma unroll
        for (int r = 0; r < 8; r++)
            #pragma unroll
            for (int cc = 0; cc < 4; cc++)
                Sg[(m0 + r) * DVV + v0 + cc] = acc[r][cc];
        if (tx == 0) {
            float* zg = g_z + (h * NC + c) * MF;
            #pragma unroll
            for (int r = 0; r < 8; r++) zg[m0 + r] = zacc[r];
        }
    }
}

// ---------------------------------------------------------------------------
// Kernel B: in-place exclusive prefix over chunks (registers; fully parallel)
// ---------------------------------------------------------------------------
__global__ void __launch_bounds__(256, 1) kB()
{
    const int h = blockIdx.x, slab = blockIdx.y, t = threadIdx.x;
    if (slab < 32) {
        const int idx = slab * 256 + t;                 // 0..8191 within S state
        float* base = g_S + (size_t)h * NC * MF * DVV + idx;
        float v[NC];
        #pragma unroll
        for (int c = 0; c < NC; c++) v[c] = base[c * (MF * DVV)];
        float run = 0.f;
        #pragma unroll
        for (int c = 0; c < NC; c++) { base[c * (MF * DVV)] = run; run += v[c]; }
    } else if (t < MF) {
        float* base = g_z + h * NC * MF + t;
        float v[NC];
        #pragma unroll
        for (int c = 0; c < NC; c++) v[c] = base[c * MF];
        float run = 0.f;
        #pragma unroll
        for (int c = 0; c < NC; c++) { base[c * MF] = run; run += v[c]; }
    }
}

// ---------------------------------------------------------------------------
// Kernel C: per (head, chunk): phi_q, phi_k, inter = phi_q @ S_prefix,
// scores = causal(phi_q @ phi_k^T), intra = scores @ V, norm, output.
// ---------------------------------------------------------------------------
// smem float offsets
#define C_OFF_PHIQ 0          // sPhiQ [i][m] 128x132 ; reused as sOut [vd][i] 64x128
#define C_OFF_PHIK 16896      // sPhiKt[m][i] 128x132 ; reused as scores [i][j] 128x132
#define C_OFF_R3   33792      // phase1: sF(8448)+sX(8192) ; phase2: sVt(8704)+sS(8192)+sz(128)
#define C_OFF_F    (C_OFF_R3)
#define C_OFF_X    (C_OFF_R3 + 8448)
#define C_OFF_VT   (C_OFF_R3)
#define C_OFF_S    (C_OFF_R3 + 8704)
#define C_OFF_Z    (C_OFF_R3 + 8704 + 8192)
#define C_SMEM_FLOATS 50816
#define C_SMEM_BYTES  (C_SMEM_FLOATS * 4)

__global__ void __launch_bounds__(256, 1)
kC(const float* __restrict__ queries, const float* __restrict__ keys,
   const float* __restrict__ values, const float* __restrict__ feat,
   float* __restrict__ out)
{
    const int c = blockIdx.x, h = blockIdx.y, t = threadIdx.x;
    extern __shared__ float sm[];
    float* sPhiQ  = sm + C_OFF_PHIQ;
    float* sPhiKt = sm + C_OFF_PHIK;   // transposed [m][i]
    float* sSc    = sm + C_OFF_PHIK;   // scores [i][j], reuses phiK region
    float* sOut   = sm + C_OFF_PHIQ;   // [vd][i], reuses phiQ region
    float* sF     = sm + C_OFF_F;
    float* sX     = sm + C_OFF_X;
    float* sVt    = sm + C_OFF_VT;
    float* sS     = sm + C_OFF_S;
    float* sz     = sm + C_OFF_Z;
    const int nbase = c * CHUNK;
    const int tx = t & 15, ty = t >> 4;

    // Phase 1a: stage F (transposed) and K chunk
    for (int idx = t; idx < MF * DK; idx += 256) {
        int m = idx >> 6, d = idx & 63;
        sF[d * 132 + m] = feat[idx];
    }
    for (int idx = t; idx < DK * CHUNK; idx += 256) {
        int d = idx >> 7, i = idx & 127;
        sX[idx] = keys[(h * DK + d) * NSEQ + nbase + i];
    }
    __syncthreads();

    // Phase 1b: phi_k GEMM, stored TRANSPOSED [m][i]
    {
        float acc[8][8];
        #pragma unroll
        for (int r = 0; r < 8; r++)
            #pragma unroll
            for (int cc = 0; cc < 8; cc++) acc[r][cc] = 0.f;
        const int i0 = ty * 8, m0 = tx * 8;
        for (int d = 0; d < DK; d++) {
            float a[8], b[8];
            #pragma unroll
            for (int r = 0; r < 8; r++)  a[r]  = sX[d * 128 + i0 + r];
            #pragma unroll
            for (int cc = 0; cc < 8; cc++) b[cc] = sF[d * 132 + m0 + cc];
            #pragma unroll
            for (int r = 0; r < 8; r++)
                #pragma unroll
                for (int cc = 0; cc < 8; cc++)
                    acc[r][cc] = fmaf(a[r], b[cc], acc[r][cc]);
        }
        __syncthreads();   // all reads of sX done before reloading it
        #pragma unroll
        for (int r = 0; r < 8; r++)
            #pragma unroll
            for (int cc = 0; cc < 8; cc++)
                sPhiKt[(m0 + cc) * 132 + i0 + r] = fmaxf(acc[r][cc], 0.f) * PHI_SCALE;
        // reload sX with Q chunk
        for (int idx = t; idx < DK * CHUNK; idx += 256) {
            int d = idx >> 7, i = idx & 127;
            sX[idx] = queries[(h * DK + d) * NSEQ + nbase + i];
        }
    }
    __syncthreads();

    // Phase 1c: phi_q GEMM, stored [i][m]; then stage V / S_prefix / z_prefix
    {
        float acc[8][8];
        #pragma unroll
        for (int r = 0; r < 8; r++)
            #pragma unroll
            for (int cc = 0; cc < 8; cc++) acc[r][cc] = 0.f;
        const int i0 = ty * 8, m0 = tx * 8;
        for (int d = 0; d < DK; d++) {
            float a[8], b[8];
            #pragma unroll
            for (int r = 0; r < 8; r++)  a[r]  = sX[d * 128 + i0 + r];
            #pragma unroll
            for (int cc = 0; cc < 8; cc++) b[cc] = sF[d * 132 + m0 + cc];
            #pragma unroll
            for (int r = 0; r < 8; r++)
                #pragma unroll
                for (int cc = 0; cc < 8; cc++)
                    acc[r][cc] = fmaf(a[r], b[cc], acc[r][cc]);
        }
        __syncthreads();   // all reads of sF/sX done before overwriting region R3
        #pragma unroll
        for (int r = 0; r < 8; r++)
            #pragma unroll
            for (int cc = 0; cc < 8; cc++)
                sPhiQ[(i0 + r) * 132 + m0 + cc] = fmaxf(acc[r][cc], 0.f) * PHI_SCALE;
        for (int idx = t; idx < DVV * CHUNK; idx += 256) {
            int d = idx >> 7, i = idx & 127;
            sVt[i * 68 + d] = values[(h * DVV + d) * NSEQ + nbase + i];
        }
        {
            const float* Sg = g_S + (size_t)((h * NC + c) * MF) * DVV;
            for (int idx = t; idx < MF * DVV; idx += 256) sS[idx] = Sg[idx];
            if (t < MF) sz[t] = g_z[(h * NC + c) * MF + t];
        }
    }
    __syncthreads();

    // Phase 2: scores[i][j] = phi_q[i] . phi_k[j]  (causal masked), into PHIK region
    {
        float acc[8][8];
        #pragma unroll
        for (int r = 0; r < 8; r++)
            #pragma unroll
            for (int cc = 0; cc < 8; cc++) acc[r][cc] = 0.f;
        const int i0 = ty * 8, j0 = tx * 8;
        for (int m = 0; m < MF; m++) {
            float a[8], b[8];
            #pragma unroll
            for (int r = 0; r < 8; r++)  a[r]  = sPhiQ [(i0 + r) * 132 + m];
            #pragma unroll
            for (int cc = 0; cc < 8; cc++) b[cc] = sPhiKt[m * 132 + j0 + cc];
            #pragma unroll
            for (int r = 0; r < 8; r++)
                #pragma unroll
                for (int cc = 0; cc < 8; cc++)
                    acc[r][cc] = fmaf(a[r], b[cc], acc[r][cc]);
        }
        __syncthreads();   // all reads of sPhiKt done before overwriting with scores
        #pragma unroll
        for (int r = 0; r < 8; r++)
            #pragma unroll
            for (int cc = 0; cc < 8; cc++)
                sSc[(i0 + r) * 132 + j0 + cc] = (j0 + cc <= i0 + r) ? acc[r][cc] : 0.f;
    }
    __syncthreads();

    // Phase 3: inter (phi_q @ S_prefix, + q.z_prefix) then intra (scores @ V, + row sums)
    {
        float acc[8][4], nacc[8];
        #pragma unroll
        for (int r = 0; r < 8; r++) {
            nacc[r] = 0.f;
            #pragma unroll
            for (int cc = 0; cc < 4; cc++) acc[r][cc] = 0.f;
        }
        const int i0 = ty * 8, v0 = tx * 4;
        for (int m = 0; m < MF; m++) {
            float a[8], b[4];
            const float zm = sz[m];
            #pragma unroll
            for (int r = 0; r < 8; r++)  a[r]  = sPhiQ[(i0 + r) * 132 + m];
            #pragma unroll
            for (int cc = 0; cc < 4; cc++) b[cc] = sS[m * DVV + v0 + cc];
            #pragma unroll
            for (int r = 0; r < 8; r++) {
                nacc[r] = fmaf(a[r], zm, nacc[r]);
                #pragma unroll
                for (int cc = 0; cc < 4; cc++)
                    acc[r][cc] = fmaf(a[r], b[cc], acc[r][cc]);
            }
        }
        for (int j = 0; j < CHUNK; j++) {
            float a[8], b[4];
            #pragma unroll
            for (int r = 0; r < 8; r++)  a[r]  = sSc[(i0 + r) * 132 + j];
            #pragma unroll
            for (int cc = 0; cc < 4; cc++) b[cc] = sVt[j * 68 + v0 + cc];
            #pragma unroll
            for (int r = 0; r < 8; r++) {
                nacc[r] += a[r];
                #pragma unroll
                for (int cc = 0; cc < 4; cc++)
                    acc[r][cc] = fmaf(a[r], b[cc], acc[r][cc]);
            }
        }
        __syncthreads();   // last readers of sPhiQ done; safe to write sOut there
        #pragma unroll
        for (int r = 0; r < 8; r++) {
            const float inv = 1.0f / nacc[r];
            #pragma unroll
            for (int cc = 0; cc < 4; cc++)
                sOut[(v0 + cc) * 128 + i0 + r] = acc[r][cc] * inv;
        }
    }
    __syncthreads();

    // Coalesced output store: out[h][vd][n]
    for (int idx = t; idx < DVV * CHUNK; idx += 256) {
        int vd = idx >> 7, i = idx & 127;
        out[(h * DVV + vd) * NSEQ + nbase + i] = sOut[idx];
    }
}

// ---------------------------------------------------------------------------
extern "C" void kernel_launch(void* const* d_in, const int* in_sizes, int n_in,
                              void* d_out, int out_size)
{
    const float* keys    = (const float*)d_in[0];
    const float* values  = (const float*)d_in[1];
    const float* queries = (const float*)d_in[2];
    const float* feat    = (const float*)d_in[3];
    float* out = (float*)d_out;

    cudaFuncSetAttribute(kA, cudaFuncAttributeMaxDynamicSharedMemorySize, A_SMEM_BYTES);
    cudaFuncSetAttribute(kC, cudaFuncAttributeMaxDynamicSharedMemorySize, C_SMEM_BYTES);

    kA<<<dim3(NC, BH), 256, A_SMEM_BYTES>>>(keys, values, feat);
    kB<<<dim3(BH, 33), 256>>>();
    kC<<<dim3(NC, BH), 256, C_SMEM_BYTES>>>(queries, keys, values, feat, out);
}

// round 5
// speedup vs baseline: 3.1713x; 3.1713x over previous
#include <cuda_runtime.h>
#include <cstdint>

#define BH    8
#define DK    64
#define DVV   64
#define NSEQ  2048
#define MF    128
#define CHUNK 128
#define NC    16
#define VP    72          // DV padded: col 64 = ones (z / norm), 65..71 = 0

#define PHI_SCALE 0.08838834764831845f   // 1/sqrt(128)

// Per-(head,chunk) fused state [S | z | pad] : [m][VP], fp32.
// kB converts to exclusive prefix over chunks.
__device__ float g_S[BH * NC * MF * VP];   // 4.7 MB

// ---------------------------------------------------------------------------
__device__ __forceinline__ uint32_t f2tf(float f) {
    uint32_t r; asm("cvt.rna.tf32.f32 %0, %1;" : "=r"(r) : "f"(f)); return r;
}
__device__ __forceinline__ void mma8(float* d, const uint32_t* A, const uint32_t* B) {
    asm volatile("mma.sync.aligned.m16n8k8.row.col.f32.tf32.tf32.f32 "
                 "{%0,%1,%2,%3}, {%4,%5,%6,%7}, {%8,%9}, {%0,%1,%2,%3};"
                 : "+f"(d[0]), "+f"(d[1]), "+f"(d[2]), "+f"(d[3])
                 : "r"(A[0]), "r"(A[1]), "r"(A[2]), "r"(A[3]), "r"(B[0]), "r"(B[1]));
}

// Smem strides (words), chosen so fragment LDS are bank-conflict-free:
// A-operand row stride ≡ 4 (mod 32); B-operand row stride ≡ 8 (mod 32).
#define STR_KQ 68    // [i][d]  A
#define STR_F  136   // [d][m]  B
#define STR_PT 132   // [m][i]  A (kA phi^T)
#define STR_V  72    // [i][v]  B
#define STR_PQ 132   // [i][m]  A
#define STR_PK 136   // [m][j]  B
#define STR_SC 132   // [i][j]  A
#define STR_ST 72    // [m][v]  B

// ===========================================================================
// Kernel A: per (h,c): phi = relu(Kc F^T)*s ;  [S|z] = phi^T [V;1]
// ===========================================================================
#define A_K   0                       // 128 x 68  = 8704
#define A_F   8704                    // 64 x 136  = 8704
#define A_PT  17408                   // 128 x 132 = 16896
#define A_V   34304                   // 128 x 72  = 9216
#define A_SMW 43520
#define A_SMB (A_SMW * 4)

__global__ void __launch_bounds__(256, 1)
kA(const float* __restrict__ keys, const float* __restrict__ values,
   const float* __restrict__ feat)
{
    extern __shared__ uint32_t sm[];
    const int t = threadIdx.x, w = t >> 5, lane = t & 31;
    const int g = lane >> 2, tg = lane & 3;
    const int c = blockIdx.x, h = blockIdx.y, nbase = c * CHUNK;

    // Stage (tf32-rounded)
    for (int idx = t; idx < DK * CHUNK; idx += 256) {
        int i = idx & 127, d = idx >> 7;
        sm[A_K + i * STR_KQ + d] = f2tf(keys[(h * DK + d) * NSEQ + nbase + i]);
    }
    for (int idx = t; idx < MF * DK; idx += 256) {
        int d = idx & 63, m = idx >> 6;
        sm[A_F + d * STR_F + m] = f2tf(feat[m * DK + d]);
    }
    for (int idx = t; idx < DVV * CHUNK; idx += 256) {
        int i = idx & 127, v = idx >> 7;
        sm[A_V + i * STR_V + v] = f2tf(values[(h * DVV + v) * NSEQ + nbase + i]);
    }
    for (int idx = t; idx < CHUNK * 8; idx += 256) {
        int i = idx >> 3, v = 64 + (idx & 7);
        sm[A_V + i * STR_V + v] = (v == 64) ? 0x3F800000u : 0u;
    }
    __syncthreads();

    // GEMM1: phi[i][m], K=64; warp tile 32x64
    {
        const int m0 = (w & 3) * 32, n0 = (w >> 2) * 64;
        float D[2][8][4] = {};
        for (int kk = 0; kk < 64; kk += 8) {
            uint32_t A[2][4], B[8][2];
            #pragma unroll
            for (int ms = 0; ms < 2; ms++) {
                int r0 = m0 + ms * 16 + g;
                A[ms][0] = sm[A_K + r0 * STR_KQ + kk + tg];
                A[ms][1] = sm[A_K + (r0 + 8) * STR_KQ + kk + tg];
                A[ms][2] = sm[A_K + r0 * STR_KQ + kk + tg + 4];
                A[ms][3] = sm[A_K + (r0 + 8) * STR_KQ + kk + tg + 4];
            }
            #pragma unroll
            for (int ns = 0; ns < 8; ns++) {
                B[ns][0] = sm[A_F + (kk + tg) * STR_F + n0 + ns * 8 + g];
                B[ns][1] = sm[A_F + (kk + tg + 4) * STR_F + n0 + ns * 8 + g];
            }
            #pragma unroll
            for (int ms = 0; ms < 2; ms++)
                #pragma unroll
                for (int ns = 0; ns < 8; ns++) mma8(D[ms][ns], A[ms], B[ns]);
        }
        // Epilogue: relu*scale -> phiT[m][i]
        #pragma unroll
        for (int ms = 0; ms < 2; ms++)
            #pragma unroll
            for (int ns = 0; ns < 8; ns++)
                #pragma unroll
                for (int e = 0; e < 4; e++) {
                    int row = m0 + ms * 16 + g + ((e >> 1) << 3);
                    int col = n0 + ns * 8 + tg * 2 + (e & 1);
                    sm[A_PT + col * STR_PT + row] =
                        f2tf(fmaxf(D[ms][ns][e], 0.f) * PHI_SCALE);
                }
    }
    __syncthreads();

    // GEMM2: [S|z][m][v+], K=128; warp tile 16x72
    {
        const int m0 = w * 16;
        float D[9][4] = {};
        for (int kk = 0; kk < CHUNK; kk += 8) {
            uint32_t A[4];
            A[0] = sm[A_PT + (m0 + g) * STR_PT + kk + tg];
            A[1] = sm[A_PT + (m0 + g + 8) * STR_PT + kk + tg];
            A[2] = sm[A_PT + (m0 + g) * STR_PT + kk + tg + 4];
            A[3] = sm[A_PT + (m0 + g + 8) * STR_PT + kk + tg + 4];
            #pragma unroll
            for (int ns = 0; ns < 9; ns++) {
                uint32_t B[2];
                B[0] = sm[A_V + (kk + tg) * STR_V + ns * 8 + g];
                B[1] = sm[A_V + (kk + tg + 4) * STR_V + ns * 8 + g];
                mma8(D[ns], A, B);
            }
        }
        float* Sg = g_S + (size_t)(h * NC + c) * MF * VP;
        #pragma unroll
        for (int ns = 0; ns < 9; ns++)
            #pragma unroll
            for (int e = 0; e < 4; e++) {
                int row = m0 + g + ((e >> 1) << 3);
                int col = ns * 8 + tg * 2 + (e & 1);
                Sg[row * VP + col] = D[ns][e];
            }
    }
}

// ===========================================================================
// Kernel B: exclusive prefix over chunks of g_S (elementwise)
// ===========================================================================
__global__ void __launch_bounds__(256, 1) kB()
{
    const int h = blockIdx.x, idx = blockIdx.y * 256 + threadIdx.x;  // < 9216
    float* base = g_S + (size_t)h * NC * MF * VP + idx;
    float v[NC];
    #pragma unroll
    for (int c = 0; c < NC; c++) v[c] = base[c * (MF * VP)];
    float run = 0.f;
    #pragma unroll
    for (int c = 0; c < NC; c++) { base[c * (MF * VP)] = run; run += v[c]; }
}

// ===========================================================================
// Kernel C: phi_k, phi_q, scores (masked), out = phiQ.S+ + Sc.V+, norm, store
// ===========================================================================
#define C_KQ  0                      // 128x68 = 8704 -> later St 128x72 @0
#define C_F   8704                   // 64x136 = 8704 -> later (St spills into)
#define C_ST  0                      // 128x72 = 9216
#define C_V   9216                   // 128x72 = 9216
#define C_PQ  18432                  // 128x132 = 16896
#define C_PK  35328                  // 128x136 = 17408 (later Sc 128x132)
#define C_SMW 52736
#define C_SMB (C_SMW * 4)

__global__ void __launch_bounds__(256, 1)
kC(const float* __restrict__ queries, const float* __restrict__ keys,
   const float* __restrict__ values, const float* __restrict__ feat,
   float* __restrict__ out)
{
    extern __shared__ uint32_t sm[];
    const int t = threadIdx.x, w = t >> 5, lane = t & 31;
    const int g = lane >> 2, tg = lane & 3;
    const int c = blockIdx.x, h = blockIdx.y, nbase = c * CHUNK;

    // a) stage K, F
    for (int idx = t; idx < DK * CHUNK; idx += 256) {
        int i = idx & 127, d = idx >> 7;
        sm[C_KQ + i * STR_KQ + d] = f2tf(keys[(h * DK + d) * NSEQ + nbase + i]);
    }
    for (int idx = t; idx < MF * DK; idx += 256) {
        int d = idx & 63, m = idx >> 6;
        sm[C_F + d * STR_F + m] = f2tf(feat[m * DK + d]);
    }
    __syncthreads();

    const int pm0 = (w & 3) * 32, pn0 = (w >> 2) * 64;

    // b) GEMM phi_k (frags)
    float DP[2][8][4] = {};
    for (int kk = 0; kk < 64; kk += 8) {
        uint32_t A[2][4], B[8][2];
        #pragma unroll
        for (int ms = 0; ms < 2; ms++) {
            int r0 = pm0 + ms * 16 + g;
            A[ms][0] = sm[C_KQ + r0 * STR_KQ + kk + tg];
            A[ms][1] = sm[C_KQ + (r0 + 8) * STR_KQ + kk + tg];
            A[ms][2] = sm[C_KQ + r0 * STR_KQ + kk + tg + 4];
            A[ms][3] = sm[C_KQ + (r0 + 8) * STR_KQ + kk + tg + 4];
        }
        #pragma unroll
        for (int ns = 0; ns < 8; ns++) {
            B[ns][0] = sm[C_F + (kk + tg) * STR_F + pn0 + ns * 8 + g];
            B[ns][1] = sm[C_F + (kk + tg + 4) * STR_F + pn0 + ns * 8 + g];
        }
        #pragma unroll
        for (int ms = 0; ms < 2; ms++)
            #pragma unroll
            for (int ns = 0; ns < 8; ns++) mma8(DP[ms][ns], A[ms], B[ns]);
    }
    __syncthreads();   // all reads of K done

    // c) epilogue phi_k -> sPK[m][j] (transposed); restage Q into C_KQ
    #pragma unroll
    for (int ms = 0; ms < 2; ms++)
        #pragma unroll
        for (int ns = 0; ns < 8; ns++)
            #pragma unroll
            for (int e = 0; e < 4; e++) {
                int rj = pm0 + ms * 16 + g + ((e >> 1) << 3);
                int cm = pn0 + ns * 8 + tg * 2 + (e & 1);
                sm[C_PK + cm * STR_PK + rj] =
                    f2tf(fmaxf(DP[ms][ns][e], 0.f) * PHI_SCALE);
            }
    for (int idx = t; idx < DK * CHUNK; idx += 256) {
        int i = idx & 127, d = idx >> 7;
        sm[C_KQ + i * STR_KQ + d] = f2tf(queries[(h * DK + d) * NSEQ + nbase + i]);
    }
    __syncthreads();

    // d) GEMM phi_q (frags)
    #pragma unroll
    for (int ms = 0; ms < 2; ms++)
        #pragma unroll
        for (int ns = 0; ns < 8; ns++)
            #pragma unroll
            for (int e = 0; e < 4; e++) DP[ms][ns][e] = 0.f;
    for (int kk = 0; kk < 64; kk += 8) {
        uint32_t A[2][4], B[8][2];
        #pragma unroll
        for (int ms = 0; ms < 2; ms++) {
            int r0 = pm0 + ms * 16 + g;
            A[ms][0] = sm[C_KQ + r0 * STR_KQ + kk + tg];
            A[ms][1] = sm[C_KQ + (r0 + 8) * STR_KQ + kk + tg];
            A[ms][2] = sm[C_KQ + r0 * STR_KQ + kk + tg + 4];
            A[ms][3] = sm[C_KQ + (r0 + 8) * STR_KQ + kk + tg + 4];
        }
        #pragma unroll
        for (int ns = 0; ns < 8; ns++) {
            B[ns][0] = sm[C_F + (kk + tg) * STR_F + pn0 + ns * 8 + g];
            B[ns][1] = sm[C_F + (kk + tg + 4) * STR_F + pn0 + ns * 8 + g];
        }
        #pragma unroll
        for (int ms = 0; ms < 2; ms++)
            #pragma unroll
            for (int ns = 0; ns < 8; ns++) mma8(DP[ms][ns], A[ms], B[ns]);
    }
    __syncthreads();   // all reads of Q/F done -> C_KQ/C_F reusable

    // e) epilogue phi_q -> sPQ[i][m]; stage St+ (prefix [S|z]) and V+
    #pragma unroll
    for (int ms = 0; ms < 2; ms++)
        #pragma unroll
        for (int ns = 0; ns < 8; ns++)
            #pragma unroll
            for (int e = 0; e < 4; e++) {
                int ri = pm0 + ms * 16 + g + ((e >> 1) << 3);
                int cm = pn0 + ns * 8 + tg * 2 + (e & 1);
                sm[C_PQ + ri * STR_PQ + cm] =
                    f2tf(fmaxf(DP[ms][ns][e], 0.f) * PHI_SCALE);
            }
    {
        const float* Sg = g_S + (size_t)(h * NC + c) * MF * VP;
        for (int idx = t; idx < MF * VP; idx += 256)
            sm[C_ST + idx] = f2tf(Sg[idx]);          // [m][v], stride 72 native
        for (int idx = t; idx < DVV * CHUNK; idx += 256) {
            int j = idx & 127, v = idx >> 7;
            sm[C_V + j * STR_V + v] = f2tf(values[(h * DVV + v) * NSEQ + nbase + j]);
        }
        for (int idx = t; idx < CHUNK * 8; idx += 256) {
            int j = idx >> 3, v = 64 + (idx & 7);
            sm[C_V + j * STR_V + v] = (v == 64) ? 0x3F800000u : 0u;
        }
    }
    __syncthreads();

    // f) GEMM scores: A=sPQ, B=sPK, K=128 (frags in DP)
    #pragma unroll
    for (int ms = 0; ms < 2; ms++)
        #pragma unroll
        for (int ns = 0; ns < 8; ns++)
            #pragma unroll
            for (int e = 0; e < 4; e++) DP[ms][ns][e] = 0.f;
    for (int kk = 0; kk < CHUNK; kk += 8) {
        uint32_t A[2][4], B[8][2];
        #pragma unroll
        for (int ms = 0; ms < 2; ms++) {
            int r0 = pm0 + ms * 16 + g;
            A[ms][0] = sm[C_PQ + r0 * STR_PQ + kk + tg];
            A[ms][1] = sm[C_PQ + (r0 + 8) * STR_PQ + kk + tg];
            A[ms][2] = sm[C_PQ + r0 * STR_PQ + kk + tg + 4];
            A[ms][3] = sm[C_PQ + (r0 + 8) * STR_PQ + kk + tg + 4];
        }
        #pragma unroll
        for (int ns = 0; ns < 8; ns++) {
            B[ns][0] = sm[C_PK + (kk + tg) * STR_PK + pn0 + ns * 8 + g];
            B[ns][1] = sm[C_PK + (kk + tg + 4) * STR_PK + pn0 + ns * 8 + g];
        }
        #pragma unroll
        for (int ms = 0; ms < 2; ms++)
            #pragma unroll
            for (int ns = 0; ns < 8; ns++) mma8(DP[ms][ns], A[ms], B[ns]);
    }
    __syncthreads();   // all reads of sPK done

    // g) epilogue scores: causal mask -> sSc[i][j] (overwrites C_PK region)
    #pragma unroll
    for (int ms = 0; ms < 2; ms++)
        #pragma unroll
        for (int ns = 0; ns < 8; ns++)
            #pragma unroll
            for (int e = 0; e < 4; e++) {
                int ri = pm0 + ms * 16 + g + ((e >> 1) << 3);
                int cj = pn0 + ns * 8 + tg * 2 + (e & 1);
                float s = (cj <= ri) ? DP[ms][ns][e] : 0.f;
                sm[C_PK + ri * STR_SC + cj] = f2tf(s);
            }
    __syncthreads();

    // h) GEMM out: [out|norm][i][v+] = phiQ.St+ + Sc.V+ ; warp tile 16x72
    {
        const int i0 = w * 16;
        float D[9][4] = {};
        for (int kk = 0; kk < CHUNK; kk += 8) {       // pass 1: phiQ . St+
            uint32_t A[4];
            A[0] = sm[C_PQ + (i0 + g) * STR_PQ + kk + tg];
            A[1] = sm[C_PQ + (i0 + g + 8) * STR_PQ + kk + tg];
            A[2] = sm[C_PQ + (i0 + g) * STR_PQ + kk + tg + 4];
            A[3] = sm[C_PQ + (i0 + g + 8) * STR_PQ + kk + tg + 4];
            #pragma unroll
            for (int ns = 0; ns < 9; ns++) {
                uint32_t B[2];
                B[0] = sm[C_ST + (kk + tg) * STR_ST + ns * 8 + g];
                B[1] = sm[C_ST + (kk + tg + 4) * STR_ST + ns * 8 + g];
                mma8(D[ns], A, B);
            }
        }
        for (int kk = 0; kk < CHUNK; kk += 8) {       // pass 2: Sc . V+
            uint32_t A[4];
            A[0] = sm[C_PK + (i0 + g) * STR_SC + kk + tg];
            A[1] = sm[C_PK + (i0 + g + 8) * STR_SC + kk + tg];
            A[2] = sm[C_PK + (i0 + g) * STR_SC + kk + tg + 4];
            A[3] = sm[C_PK + (i0 + g + 8) * STR_SC + kk + tg + 4];
            #pragma unroll
            for (int ns = 0; ns < 9; ns++) {
                uint32_t B[2];
                B[0] = sm[C_V + (kk + tg) * STR_V + ns * 8 + g];
                B[1] = sm[C_V + (kk + tg + 4) * STR_V + ns * 8 + g];
                mma8(D[ns], A, B);
            }
        }
        // i) norm = column 64 (ns=8, tg=0, e=0/2) -> broadcast within row group
        float nlo = __shfl_sync(0xffffffffu, D[8][0], lane & 28);
        float nhi = __shfl_sync(0xffffffffu, D[8][2], lane & 28);
        float ilo = 1.f / nlo, ihi = 1.f / nhi;
        #pragma unroll
        for (int ns = 0; ns < 8; ns++)
            #pragma unroll
            for (int e = 0; e < 4; e++) {
                int ri = i0 + g + ((e >> 1) << 3);
                int v  = ns * 8 + tg * 2 + (e & 1);
                out[(h * DVV + v) * NSEQ + nbase + ri] =
                    D[ns][e] * ((e >> 1) ? ihi : ilo);
            }
    }
}

// ===========================================================================
extern "C" void kernel_launch(void* const* d_in, const int* in_sizes, int n_in,
                              void* d_out, int out_size)
{
    const float* keys    = (const float*)d_in[0];
    const float* values  = (const float*)d_in[1];
    const float* queries = (const float*)d_in[2];
    const float* feat    = (const float*)d_in[3];
    float* out = (float*)d_out;

    cudaFuncSetAttribute(kA, cudaFuncAttributeMaxDynamicSharedMemorySize, A_SMB);
    cudaFuncSetAttribute(kC, cudaFuncAttributeMaxDynamicSharedMemorySize, C_SMB);

    kA<<<dim3(NC, BH), 256, A_SMB>>>(keys, values, feat);
    kB<<<dim3(BH, 36), 256>>>();
    kC<<<dim3(NC, BH), 256, C_SMB>>>(queries, keys, values, feat, out);
}